// round 6
// baseline (speedup 1.0000x reference)
#include <cuda_runtime.h>
#include <math.h>
#include <stdint.h>

#define Nn 50000
#define Ee 640000
#define Dd 128
#define FFd 256
#define CC 5
#define LL 6
#define BN_EPS 1e-5f

// ---------------- static scratch (no allocations allowed) ----------------
__device__ float g_X[(size_t)Nn * Dd];
__device__ float g_Q[(size_t)Nn * Dd];
__device__ float g_K[(size_t)Nn * Dd];
__device__ float g_V[(size_t)Nn * Dd];
__device__ float g_ATT[(size_t)Nn * Dd];
__device__ float g_A[(size_t)Nn * Dd];
__device__ float g_Hbuf[(size_t)Nn * FFd];
__device__ float g_T[(size_t)Nn * Dd];

__device__ int g_cnt[Nn];
__device__ int g_fill[Nn];
__device__ int g_rowptr[Nn + 1];
__device__ int g_esrc[Ee];

__device__ float g_sum[Dd];
__device__ float g_sumsq[Dd];
__device__ float g_scale[Dd];
__device__ float g_shift[Dd];

// ---------------- CSR build ----------------
__global__ void zero_csr_kernel() {
    int i = blockIdx.x * blockDim.x + threadIdx.x;
    int stride = gridDim.x * blockDim.x;
    for (; i < Nn; i += stride) { g_cnt[i] = 0; g_fill[i] = 0; }
}

__global__ void count_kernel(const int* __restrict__ dst) {
    int e = blockIdx.x * blockDim.x + threadIdx.x;
    if (e < Ee) atomicAdd(&g_cnt[dst[e]], 1);
}

// single-block fused exclusive scan over 50001 entries (49 chunks of 1024)
__global__ void scan_fused_kernel() {
    __shared__ int s[1024];
    __shared__ int carry;
    int tid = threadIdx.x;
    if (tid == 0) { carry = 0; g_rowptr[0] = 0; }
    __syncthreads();
    for (int c = 0; c < 49; c++) {
        int i = c * 1024 + tid;
        int v = (i < Nn) ? g_cnt[i] : 0;
        s[tid] = v;
        __syncthreads();
        for (int off = 1; off < 1024; off <<= 1) {
            int t = 0;
            if (tid >= off) t = s[tid - off];
            __syncthreads();
            s[tid] += t;
            __syncthreads();
        }
        if (i < Nn) g_rowptr[i + 1] = s[tid] + carry;
        __syncthreads();
        if (tid == 1023) carry += s[1023];
        __syncthreads();
    }
}

__global__ void fill_kernel(const int* __restrict__ src, const int* __restrict__ dst) {
    int e = blockIdx.x * blockDim.x + threadIdx.x;
    if (e < Ee) {
        int d = dst[e];
        int pos = atomicAdd(&g_fill[d], 1);
        g_esrc[g_rowptr[d] + pos] = src[e];
    }
}

// ---------------- 3xTF32 tensor-core GEMM ----------------
// C[M,Nc] = A[M,K] @ B[K,Nc] (+bias)(+relu). BM=BN=128, BK=8, 256 threads.
// Each fp32 operand split into hi+lo tf32 at STS time; per tile:
//   D += Ahi*Bhi + Alo*Bhi + Ahi*Blo   (error ~2^-21)
// blockIdx.z selects (B,C) pair -> fused QKV in one launch.
__device__ __forceinline__ void split_tf32(float x, uint32_t& hi, uint32_t& lo) {
    asm("cvt.rna.tf32.f32 %0, %1;" : "=r"(hi) : "f"(x));
    float r = x - __uint_as_float(hi);
    asm("cvt.rna.tf32.f32 %0, %1;" : "=r"(lo) : "f"(r));
}

__device__ __forceinline__ void mma_tf32(float* d, const uint32_t* a, uint32_t b0, uint32_t b1) {
    asm volatile(
        "mma.sync.aligned.m16n8k8.row.col.f32.tf32.tf32.f32 "
        "{%0,%1,%2,%3}, {%4,%5,%6,%7}, {%8,%9}, {%0,%1,%2,%3};"
        : "+f"(d[0]), "+f"(d[1]), "+f"(d[2]), "+f"(d[3])
        : "r"(a[0]), "r"(a[1]), "r"(a[2]), "r"(a[3]), "r"(b0), "r"(b1));
}

#define LDA 136
#define LDB 136

__global__ __launch_bounds__(256) void gemm_kernel(
    const float* __restrict__ A,
    const float* __restrict__ B0, const float* __restrict__ B1, const float* __restrict__ B2,
    const float* __restrict__ bias,
    float* __restrict__ C0, float* __restrict__ C1, float* __restrict__ C2,
    int M, int K, int Nc, int fuseRelu)
{
    const float* B = (blockIdx.z == 0) ? B0 : ((blockIdx.z == 1) ? B1 : B2);
    float* C = (blockIdx.z == 0) ? C0 : ((blockIdx.z == 1) ? C1 : C2);

    __shared__ float Ahi[2][8][LDA];
    __shared__ float Alo[2][8][LDA];
    __shared__ float Bhi[2][8][LDB];
    __shared__ float Blo[2][8][LDB];

    const int tid = threadIdx.x;
    const int bm = blockIdx.x * 128;
    const int bn = blockIdx.y * 128;

    const int lane = tid & 31;
    const int gid = lane >> 2;      // 0..7
    const int t4 = lane & 3;        // 0..3
    const int wid = tid >> 5;       // 0..7
    const int wm = wid & 3;         // 0..3 -> 32-row slab
    const int wn = wid >> 2;        // 0..1 -> 64-col slab
    const int m0 = wm * 32;
    const int n0 = wn * 64;

    // loader mapping
    const int arow = tid >> 1;             // 0..127
    const int ac4 = (tid & 1) * 4;         // 0 or 4
    const bool aval = (bm + arow) < M;
    const float* Aptr = A + (size_t)(bm + arow) * K + ac4;
    const int brow = tid >> 5;             // 0..7
    const int bc4 = (tid & 31) * 4;        // 0..124
    const float* Bptr = B + (size_t)brow * Nc + bn + bc4;

    float acc[2][8][4];
#pragma unroll
    for (int mt = 0; mt < 2; mt++)
#pragma unroll
        for (int nt = 0; nt < 8; nt++)
#pragma unroll
            for (int r = 0; r < 4; r++) acc[mt][nt][r] = 0.f;

    // ---- preload stage 0 ----
    {
        float4 av = make_float4(0.f, 0.f, 0.f, 0.f);
        if (aval) av = *(const float4*)(Aptr);
        float4 bv = *(const float4*)(Bptr);
        uint32_t h, l;
        split_tf32(av.x, h, l); Ahi[0][ac4 + 0][arow] = __uint_as_float(h); Alo[0][ac4 + 0][arow] = __uint_as_float(l);
        split_tf32(av.y, h, l); Ahi[0][ac4 + 1][arow] = __uint_as_float(h); Alo[0][ac4 + 1][arow] = __uint_as_float(l);
        split_tf32(av.z, h, l); Ahi[0][ac4 + 2][arow] = __uint_as_float(h); Alo[0][ac4 + 2][arow] = __uint_as_float(l);
        split_tf32(av.w, h, l); Ahi[0][ac4 + 3][arow] = __uint_as_float(h); Alo[0][ac4 + 3][arow] = __uint_as_float(l);
        uint32_t h0, l0, h1, l1, h2, l2, h3, l3;
        split_tf32(bv.x, h0, l0); split_tf32(bv.y, h1, l1);
        split_tf32(bv.z, h2, l2); split_tf32(bv.w, h3, l3);
        *(uint4*)&Bhi[0][brow][bc4] = make_uint4(h0, h1, h2, h3);
        *(uint4*)&Blo[0][brow][bc4] = make_uint4(l0, l1, l2, l3);
    }
    __syncthreads();

    int cur = 0;
    for (int k0 = 0; k0 < K; k0 += 8) {
        const bool has = (k0 + 8) < K;
        float4 av, bv;
        if (has) {
            av = make_float4(0.f, 0.f, 0.f, 0.f);
            if (aval) av = *(const float4*)(Aptr + k0 + 8);
            bv = *(const float4*)(Bptr + (size_t)(k0 + 8) * Nc);
        }

        // ---- compute on stage `cur` ----
        uint32_t ah[2][4], al[2][4];
#pragma unroll
        for (int mt = 0; mt < 2; mt++) {
            int mb = m0 + mt * 16 + gid;
            ah[mt][0] = __float_as_uint(Ahi[cur][t4][mb]);
            ah[mt][1] = __float_as_uint(Ahi[cur][t4][mb + 8]);
            ah[mt][2] = __float_as_uint(Ahi[cur][t4 + 4][mb]);
            ah[mt][3] = __float_as_uint(Ahi[cur][t4 + 4][mb + 8]);
            al[mt][0] = __float_as_uint(Alo[cur][t4][mb]);
            al[mt][1] = __float_as_uint(Alo[cur][t4][mb + 8]);
            al[mt][2] = __float_as_uint(Alo[cur][t4 + 4][mb]);
            al[mt][3] = __float_as_uint(Alo[cur][t4 + 4][mb + 8]);
        }
#pragma unroll
        for (int nt = 0; nt < 8; nt++) {
            int nb = n0 + nt * 8 + gid;
            uint32_t bh0 = __float_as_uint(Bhi[cur][t4][nb]);
            uint32_t bh1 = __float_as_uint(Bhi[cur][t4 + 4][nb]);
            uint32_t bl0 = __float_as_uint(Blo[cur][t4][nb]);
            uint32_t bl1 = __float_as_uint(Blo[cur][t4 + 4][nb]);
#pragma unroll
            for (int mt = 0; mt < 2; mt++) {
                mma_tf32(acc[mt][nt], ah[mt], bh0, bh1);
                mma_tf32(acc[mt][nt], al[mt], bh0, bh1);
                mma_tf32(acc[mt][nt], ah[mt], bl0, bl1);
            }
        }

        if (has) {
            int nxt = cur ^ 1;
            uint32_t h, l;
            split_tf32(av.x, h, l); Ahi[nxt][ac4 + 0][arow] = __uint_as_float(h); Alo[nxt][ac4 + 0][arow] = __uint_as_float(l);
            split_tf32(av.y, h, l); Ahi[nxt][ac4 + 1][arow] = __uint_as_float(h); Alo[nxt][ac4 + 1][arow] = __uint_as_float(l);
            split_tf32(av.z, h, l); Ahi[nxt][ac4 + 2][arow] = __uint_as_float(h); Alo[nxt][ac4 + 2][arow] = __uint_as_float(l);
            split_tf32(av.w, h, l); Ahi[nxt][ac4 + 3][arow] = __uint_as_float(h); Alo[nxt][ac4 + 3][arow] = __uint_as_float(l);
            uint32_t h0, l0, h1, l1, h2, l2, h3, l3;
            split_tf32(bv.x, h0, l0); split_tf32(bv.y, h1, l1);
            split_tf32(bv.z, h2, l2); split_tf32(bv.w, h3, l3);
            *(uint4*)&Bhi[nxt][brow][bc4] = make_uint4(h0, h1, h2, h3);
            *(uint4*)&Blo[nxt][brow][bc4] = make_uint4(l0, l1, l2, l3);
            __syncthreads();
            cur = nxt;
        }
    }

    // ---- epilogue ----
#pragma unroll
    for (int mt = 0; mt < 2; mt++) {
        int r0 = bm + m0 + mt * 16 + gid;
        int r1 = r0 + 8;
#pragma unroll
        for (int nt = 0; nt < 8; nt++) {
            int col = bn + n0 + nt * 8 + t4 * 2;
            float bx = 0.f, by = 0.f;
            if (bias) { float2 bb = *(const float2*)&bias[col]; bx = bb.x; by = bb.y; }
            float v0 = acc[mt][nt][0] + bx;
            float v1 = acc[mt][nt][1] + by;
            float v2 = acc[mt][nt][2] + bx;
            float v3 = acc[mt][nt][3] + by;
            if (fuseRelu) {
                v0 = fmaxf(v0, 0.f); v1 = fmaxf(v1, 0.f);
                v2 = fmaxf(v2, 0.f); v3 = fmaxf(v3, 0.f);
            }
            if (r0 < M) { float2 o = make_float2(v0, v1); *(float2*)&C[(size_t)r0 * Nc + col] = o; }
            if (r1 < M) { float2 o = make_float2(v2, v3); *(float2*)&C[(size_t)r1 * Nc + col] = o; }
        }
    }
}

// ---------------- edge-restricted MHA: one warp per dst node, online softmax ----------------
__global__ __launch_bounds__(256) void attn_kernel(
    const float* __restrict__ q, const float* __restrict__ k,
    const float* __restrict__ v, float* __restrict__ out)
{
    int gwarp = (blockIdx.x * blockDim.x + threadIdx.x) >> 5;
    if (gwarp >= Nn) return;
    int lane = threadIdx.x & 31;

    float4 qv = *(const float4*)(q + (size_t)gwarp * Dd + lane * 4);
    float m = -INFINITY;
    float l = 0.f;
    float4 acc = make_float4(0.f, 0.f, 0.f, 0.f);

    int beg = g_rowptr[gwarp];
    int end = g_rowptr[gwarp + 1];
    for (int it = beg; it < end; it++) {
        int sn = g_esrc[it];
        const float4 kv = *(const float4*)(k + (size_t)sn * Dd + lane * 4);
        float partial = qv.x * kv.x + qv.y * kv.y + qv.z * kv.z + qv.w * kv.w;
        partial += __shfl_xor_sync(0xffffffffu, partial, 1);
        partial += __shfl_xor_sync(0xffffffffu, partial, 2);
        float s = partial * 0.25f;   // 1/sqrt(16)
        float nm = fmaxf(m, s);
        float sc = __expf(m - nm);
        float p = __expf(s - nm);
        const float4 vv = *(const float4*)(v + (size_t)sn * Dd + lane * 4);
        l = l * sc + p;
        acc.x = acc.x * sc + p * vv.x;
        acc.y = acc.y * sc + p * vv.y;
        acc.z = acc.z * sc + p * vv.z;
        acc.w = acc.w * sc + p * vv.w;
        m = nm;
    }
    float inv = (l > 0.f) ? (1.f / l) : 0.f;
    float4 o = make_float4(acc.x * inv, acc.y * inv, acc.z * inv, acc.w * inv);
    *(float4*)(out + (size_t)gwarp * Dd + lane * 4) = o;
}

// ---------------- BatchNorm (training-mode, over node dim) ----------------
__global__ void zero_sums_kernel() {
    int t = threadIdx.x;
    if (t < Dd) { g_sum[t] = 0.f; g_sumsq[t] = 0.f; }
}

__global__ void bn_reduce_kernel(const float* __restrict__ a, const float* __restrict__ b) {
    int col = threadIdx.x;  // 128 threads
    int rows = (Nn + gridDim.x - 1) / gridDim.x;
    int r0 = blockIdx.x * rows;
    int r1 = r0 + rows; if (r1 > Nn) r1 = Nn;
    float s = 0.f, s2 = 0.f;
    for (int r = r0; r < r1; r++) {
        float t = a[(size_t)r * Dd + col] + b[(size_t)r * Dd + col];
        s += t;
        s2 += t * t;
    }
    atomicAdd(&g_sum[col], s);
    atomicAdd(&g_sumsq[col], s2);
}

__global__ void bn_finalize_kernel(const float* __restrict__ gamma, const float* __restrict__ beta) {
    int c = threadIdx.x;
    if (c < Dd) {
        float mean = g_sum[c] / (float)Nn;
        float var = g_sumsq[c] / (float)Nn - mean * mean;
        float rstd = rsqrtf(var + BN_EPS);
        float sc = rstd * gamma[c];
        g_scale[c] = sc;
        g_shift[c] = beta[c] - mean * sc;
    }
}

__global__ void bn_apply_kernel(const float* __restrict__ a, const float* __restrict__ b,
                                float* __restrict__ o) {
    size_t idx = (size_t)blockIdx.x * blockDim.x + threadIdx.x;
    size_t stride = (size_t)gridDim.x * blockDim.x;
    size_t total = (size_t)Nn * Dd;
    for (; idx < total; idx += stride) {
        int col = (int)(idx & (Dd - 1));
        o[idx] = (a[idx] + b[idx]) * g_scale[col] + g_shift[col];
    }
}

// ---------------- final projection [N,128] @ [128,5] + bias ----------------
__global__ void proj_kernel(const float* __restrict__ x, const float* __restrict__ Wp,
                            const float* __restrict__ bp, float* __restrict__ out) {
    __shared__ float w[Dd * CC];
    for (int i = threadIdx.x; i < Dd * CC; i += blockDim.x) w[i] = Wp[i];
    __syncthreads();
    int n = blockIdx.x * blockDim.x + threadIdx.x;
    if (n >= Nn) return;
    float acc[CC];
#pragma unroll
    for (int c = 0; c < CC; c++) acc[c] = bp[c];
    const float* xr = x + (size_t)n * Dd;
    for (int kk = 0; kk < Dd; kk += 4) {
        float4 xv = *(const float4*)(xr + kk);
#pragma unroll
        for (int c = 0; c < CC; c++) {
            acc[c] += xv.x * w[(kk + 0) * CC + c];
            acc[c] += xv.y * w[(kk + 1) * CC + c];
            acc[c] += xv.z * w[(kk + 2) * CC + c];
            acc[c] += xv.w * w[(kk + 3) * CC + c];
        }
    }
#pragma unroll
    for (int c = 0; c < CC; c++) out[(size_t)n * CC + c] = acc[c];
}

// ---------------- driver ----------------
extern "C" void kernel_launch(void* const* d_in, const int* in_sizes, int n_in,
                              void* d_out, int out_size) {
    const float* x_in = (const float*)d_in[0];
    const int* eidx = (const int*)d_in[1];
    const float* Wq = (const float*)d_in[2];
    const float* Wk = (const float*)d_in[3];
    const float* Wv = (const float*)d_in[4];
    const float* Wo = (const float*)d_in[5];
    const float* g1 = (const float*)d_in[6];
    const float* bn1 = (const float*)d_in[7];
    const float* W1 = (const float*)d_in[8];
    const float* bf1 = (const float*)d_in[9];
    const float* W2 = (const float*)d_in[10];
    const float* bf2 = (const float*)d_in[11];
    const float* g2 = (const float*)d_in[12];
    const float* bn2 = (const float*)d_in[13];
    const float* Wp = (const float*)d_in[14];
    const float* bp = (const float*)d_in[15];
    float* out = (float*)d_out;

    const int* src = eidx;        // edge_index[0]
    const int* dst = eidx + Ee;   // edge_index[1]

    const int MB = (Nn + 127) / 128;       // 391
    dim3 gridQKV(MB, 1, 3);                 // fused Q/K/V via blockIdx.z
    dim3 grid128(MB, 1, 1);
    dim3 gridFF1(MB, 2, 1);
    int attnBlocks = (Nn * 32 + 255) / 256;

    // launches 1-4: CSR build
    zero_csr_kernel<<<256, 256>>>();                       // 1
    count_kernel<<<(Ee + 255) / 256, 256>>>(dst);          // 2
    scan_fused_kernel<<<1, 1024>>>();                      // 3
    fill_kernel<<<(Ee + 255) / 256, 256>>>(src, dst);      // 4

    // launch 5: layer-0 fused QKV GEMM (reads x_in directly)
    gemm_kernel<<<gridQKV, 256>>>(x_in, Wq, Wk, Wv, nullptr,
                                  g_Q, g_K, g_V, Nn, Dd, Dd, 0);

    // launch 6: attn -> this is what ncu (-s 5 -c 1) captures next round
    attn_kernel<<<attnBlocks, 256>>>(g_Q, g_K, g_V, g_ATT);

    for (int i = 0; i < LL; i++) {
        const float* Wo_i = Wo + (size_t)i * Dd * Dd;
        const float* W1_i = W1 + (size_t)i * Dd * FFd;
        const float* W2_i = W2 + (size_t)i * FFd * Dd;
        const float* res = (i == 0) ? x_in : g_X;   // layer-0 residual is the raw input

        if (i > 0) {
            gemm_kernel<<<gridQKV, 256>>>(g_X,
                                          Wq + (size_t)i * Dd * Dd,
                                          Wk + (size_t)i * Dd * Dd,
                                          Wv + (size_t)i * Dd * Dd,
                                          nullptr, g_Q, g_K, g_V, Nn, Dd, Dd, 0);
            attn_kernel<<<attnBlocks, 256>>>(g_Q, g_K, g_V, g_ATT);
        }

        gemm_kernel<<<grid128, 256>>>(g_ATT, Wo_i, nullptr, nullptr, nullptr,
                                      g_A, nullptr, nullptr, Nn, Dd, Dd, 0);

        // x = BN(a + res)
        zero_sums_kernel<<<1, 128>>>();
        bn_reduce_kernel<<<256, 128>>>(g_A, res);
        bn_finalize_kernel<<<1, 128>>>(g1 + (size_t)i * Dd, bn1 + (size_t)i * Dd);
        bn_apply_kernel<<<2048, 256>>>(g_A, res, g_X);

        // h = relu(x@W1 + bf1); t = h@W2 + bf2
        gemm_kernel<<<gridFF1, 256>>>(g_X, W1_i, nullptr, nullptr, bf1 + (size_t)i * FFd,
                                      g_Hbuf, nullptr, nullptr, Nn, Dd, FFd, 1);
        gemm_kernel<<<grid128, 256>>>(g_Hbuf, W2_i, nullptr, nullptr, bf2 + (size_t)i * Dd,
                                      g_T, nullptr, nullptr, Nn, FFd, Dd, 0);

        // x = BN(x + t)
        zero_sums_kernel<<<1, 128>>>();
        bn_reduce_kernel<<<256, 128>>>(g_X, g_T);
        bn_finalize_kernel<<<1, 128>>>(g2 + (size_t)i * Dd, bn2 + (size_t)i * Dd);
        bn_apply_kernel<<<2048, 256>>>(g_X, g_T, g_X);
    }

    proj_kernel<<<(Nn + 255) / 256, 256>>>(g_X, Wp, bp, out);

    (void)in_sizes; (void)n_in; (void)out_size;
}

// round 9
// speedup vs baseline: 1.1357x; 1.1357x over previous
#include <cuda_runtime.h>
#include <math.h>
#include <stdint.h>

#define Nn 50000
#define Ee 640000
#define Dd 128
#define FFd 256
#define CC 5
#define LL 6
#define BN_EPS 1e-5f

// ---------------- static scratch (no allocations allowed) ----------------
__device__ float g_X[(size_t)Nn * Dd];
__device__ float g_Q[(size_t)Nn * Dd];
__device__ float g_K[(size_t)Nn * Dd];
__device__ float g_V[(size_t)Nn * Dd];
__device__ float g_ATT[(size_t)Nn * Dd];
__device__ float g_A[(size_t)Nn * Dd];
__device__ float g_Hbuf[(size_t)Nn * FFd];
__device__ float g_T[(size_t)Nn * Dd];

__device__ int g_cnt[Nn];
__device__ int g_fill[Nn];
__device__ int g_rowptr[Nn + 1];
__device__ int g_esrc[Ee];

__device__ float g_sum[Dd];
__device__ float g_sumsq[Dd];
__device__ float g_scale[Dd];
__device__ float g_shift[Dd];

// ---------------- CSR build: ONE single-block kernel (phases split by __syncthreads) ----
__global__ void csr_build_kernel(const int* __restrict__ src, const int* __restrict__ dst) {
    __shared__ int s[1024];
    __shared__ int carry;
    const int tid = threadIdx.x;

    // phase 1: zero
    for (int i = tid; i < Nn; i += 1024) { g_cnt[i] = 0; g_fill[i] = 0; }
    __syncthreads();

    // phase 2: count
    for (int e = tid; e < Ee; e += 1024) atomicAdd(&g_cnt[dst[e]], 1);
    __syncthreads();

    // phase 3: exclusive scan into g_rowptr (49 chunks of 1024)
    if (tid == 0) { carry = 0; g_rowptr[0] = 0; }
    __syncthreads();
    for (int c = 0; c < 49; c++) {
        int i = c * 1024 + tid;
        int v = (i < Nn) ? g_cnt[i] : 0;
        s[tid] = v;
        __syncthreads();
        for (int off = 1; off < 1024; off <<= 1) {
            int t = 0;
            if (tid >= off) t = s[tid - off];
            __syncthreads();
            s[tid] += t;
            __syncthreads();
        }
        if (i < Nn) g_rowptr[i + 1] = s[tid] + carry;
        __syncthreads();
        if (tid == 1023) carry += s[1023];
        __syncthreads();
    }

    // phase 4: fill
    for (int e = tid; e < Ee; e += 1024) {
        int d = dst[e];
        int pos = atomicAdd(&g_fill[d], 1);
        g_esrc[g_rowptr[d] + pos] = src[e];
    }
}

// ---------------- GEMM: C[M,Nc] = A[M,K] @ B[K,Nc] (+bias)(+relu) ----------------
// BM=BN=128, BK=8, 256 threads, 8x8 per thread, fp32, double-buffered smem.
// blockIdx.z selects (B,C) pair -> fused QKV in one launch. (R4-proven index math.)
__global__ __launch_bounds__(256) void gemm_kernel(
    const float* __restrict__ A,
    const float* __restrict__ B0, const float* __restrict__ B1, const float* __restrict__ B2,
    const float* __restrict__ bias,
    float* __restrict__ C0, float* __restrict__ C1, float* __restrict__ C2,
    int M, int K, int Nc, int fuseRelu)
{
    const float* B = (blockIdx.z == 0) ? B0 : ((blockIdx.z == 1) ? B1 : B2);
    float* C = (blockIdx.z == 0) ? C0 : ((blockIdx.z == 1) ? C1 : C2);

    __shared__ float As[2][8][128];
    __shared__ float Bs[2][8][128];
    int tid = threadIdx.x;
    int bm = blockIdx.x * 128;
    int bn = blockIdx.y * 128;
    int tx = tid & 15;
    int ty = tid >> 4;
    float acc[8][8];
#pragma unroll
    for (int i = 0; i < 8; i++)
#pragma unroll
        for (int j = 0; j < 8; j++) acc[i][j] = 0.f;

    int arow = tid >> 1;
    int acol = (tid & 1) * 4;
    int brow = tid >> 5;
    int bcol = (tid & 31) * 4;
    int garow = bm + arow;
    const bool aval = garow < M;
    const float* Aptr = A + (size_t)garow * K + acol;
    const float* Bptr = B + (size_t)brow * Nc + bn + bcol;

    // preload tile 0
    float4 av = make_float4(0.f, 0.f, 0.f, 0.f);
    if (aval) av = *(const float4*)(Aptr);
    float4 bv = *(const float4*)(Bptr);
    As[0][acol + 0][arow] = av.x;
    As[0][acol + 1][arow] = av.y;
    As[0][acol + 2][arow] = av.z;
    As[0][acol + 3][arow] = av.w;
    *(float4*)&Bs[0][brow][bcol] = bv;
    __syncthreads();

    int buf = 0;
    for (int k0 = 0; k0 < K; k0 += 8) {
        const int nk = k0 + 8;
        const bool has = nk < K;
        float4 av2, bv2;
        if (has) {
            av2 = make_float4(0.f, 0.f, 0.f, 0.f);
            if (aval) av2 = *(const float4*)(Aptr + nk);
            bv2 = *(const float4*)(Bptr + (size_t)nk * Nc);
        }
#pragma unroll
        for (int k = 0; k < 8; k++) {
            float ar[8], br[8];
            *(float4*)&ar[0] = *(const float4*)&As[buf][k][ty * 8];
            *(float4*)&ar[4] = *(const float4*)&As[buf][k][ty * 8 + 4];
            *(float4*)&br[0] = *(const float4*)&Bs[buf][k][tx * 8];
            *(float4*)&br[4] = *(const float4*)&Bs[buf][k][tx * 8 + 4];
#pragma unroll
            for (int i = 0; i < 8; i++)
#pragma unroll
                for (int j = 0; j < 8; j++) acc[i][j] += ar[i] * br[j];
        }
        if (has) {
            int nb = buf ^ 1;
            As[nb][acol + 0][arow] = av2.x;
            As[nb][acol + 1][arow] = av2.y;
            As[nb][acol + 2][arow] = av2.z;
            As[nb][acol + 3][arow] = av2.w;
            *(float4*)&Bs[nb][brow][bcol] = bv2;
            __syncthreads();
            buf = nb;
        }
    }

    float bvals[8];
#pragma unroll
    for (int j = 0; j < 8; j++) bvals[j] = bias ? bias[bn + tx * 8 + j] : 0.f;

#pragma unroll
    for (int i = 0; i < 8; i++) {
        int row = bm + ty * 8 + i;
        if (row < M) {
            float o[8];
#pragma unroll
            for (int j = 0; j < 8; j++) {
                float v = acc[i][j] + bvals[j];
                if (fuseRelu) v = fmaxf(v, 0.f);
                o[j] = v;
            }
            float* cp = C + (size_t)row * Nc + bn + tx * 8;
            *(float4*)cp = *(float4*)&o[0];
            *(float4*)(cp + 4) = *(float4*)&o[4];
        }
    }
}

// ---------------- edge-restricted MHA: one warp per dst node, online softmax ----------------
// 2-edge unrolled: halves the serial chain per edge, doubles load MLP.
__global__ __launch_bounds__(256) void attn_kernel(
    const float* __restrict__ q, const float* __restrict__ k,
    const float* __restrict__ v, float* __restrict__ out)
{
    int gwarp = (blockIdx.x * blockDim.x + threadIdx.x) >> 5;
    if (gwarp >= Nn) return;
    int lane = threadIdx.x & 31;

    float4 qv = *(const float4*)(q + (size_t)gwarp * Dd + lane * 4);
    float m = -INFINITY;
    float l = 0.f;
    float4 acc = make_float4(0.f, 0.f, 0.f, 0.f);

    const int beg = g_rowptr[gwarp];
    const int end = g_rowptr[gwarp + 1];
    int it = beg;

    for (; it + 2 <= end; it += 2) {
        int sn0 = g_esrc[it];
        int sn1 = g_esrc[it + 1];
        const float* b0 = k + (size_t)sn0 * Dd + lane * 4;
        const float* b1 = k + (size_t)sn1 * Dd + lane * 4;
        const float4 kv0 = *(const float4*)b0;
        const float4 kv1 = *(const float4*)b1;
        const float4 vv0 = *(const float4*)(v + (size_t)sn0 * Dd + lane * 4);
        const float4 vv1 = *(const float4*)(v + (size_t)sn1 * Dd + lane * 4);

        float p0 = qv.x * kv0.x + qv.y * kv0.y + qv.z * kv0.z + qv.w * kv0.w;
        float p1 = qv.x * kv1.x + qv.y * kv1.y + qv.z * kv1.z + qv.w * kv1.w;
        p0 += __shfl_xor_sync(0xffffffffu, p0, 1);
        p1 += __shfl_xor_sync(0xffffffffu, p1, 1);
        p0 += __shfl_xor_sync(0xffffffffu, p0, 2);
        p1 += __shfl_xor_sync(0xffffffffu, p1, 2);
        float s0 = p0 * 0.25f;
        float s1 = p1 * 0.25f;

        float nm = fmaxf(m, fmaxf(s0, s1));
        float sc = __expf(m - nm);
        float e0 = __expf(s0 - nm);
        float e1 = __expf(s1 - nm);
        l = l * sc + e0 + e1;
        acc.x = acc.x * sc + e0 * vv0.x + e1 * vv1.x;
        acc.y = acc.y * sc + e0 * vv0.y + e1 * vv1.y;
        acc.z = acc.z * sc + e0 * vv0.z + e1 * vv1.z;
        acc.w = acc.w * sc + e0 * vv0.w + e1 * vv1.w;
        m = nm;
    }

    if (it < end) {
        int sn = g_esrc[it];
        const float4 kv = *(const float4*)(k + (size_t)sn * Dd + lane * 4);
        const float4 vv = *(const float4*)(v + (size_t)sn * Dd + lane * 4);
        float p = qv.x * kv.x + qv.y * kv.y + qv.z * kv.z + qv.w * kv.w;
        p += __shfl_xor_sync(0xffffffffu, p, 1);
        p += __shfl_xor_sync(0xffffffffu, p, 2);
        float ss = p * 0.25f;
        float nm = fmaxf(m, ss);
        float sc = __expf(m - nm);
        float e = __expf(ss - nm);
        l = l * sc + e;
        acc.x = acc.x * sc + e * vv.x;
        acc.y = acc.y * sc + e * vv.y;
        acc.z = acc.z * sc + e * vv.z;
        acc.w = acc.w * sc + e * vv.w;
        m = nm;
    }

    float inv = (l > 0.f) ? (1.f / l) : 0.f;
    float4 o = make_float4(acc.x * inv, acc.y * inv, acc.z * inv, acc.w * inv);
    *(float4*)(out + (size_t)gwarp * Dd + lane * 4) = o;
}

// ---------------- BatchNorm (training-mode, over node dim) ----------------
__global__ void zero_sums_kernel() {
    int t = threadIdx.x;
    if (t < Dd) { g_sum[t] = 0.f; g_sumsq[t] = 0.f; }
}

__global__ void bn_reduce_kernel(const float* __restrict__ a, const float* __restrict__ b) {
    int col = threadIdx.x;  // 128 threads
    int rows = (Nn + gridDim.x - 1) / gridDim.x;
    int r0 = blockIdx.x * rows;
    int r1 = r0 + rows; if (r1 > Nn) r1 = Nn;
    float s = 0.f, s2 = 0.f;
    for (int r = r0; r < r1; r++) {
        float t = a[(size_t)r * Dd + col] + b[(size_t)r * Dd + col];
        s += t;
        s2 += t * t;
    }
    atomicAdd(&g_sum[col], s);
    atomicAdd(&g_sumsq[col], s2);
}

__global__ void bn_finalize_kernel(const float* __restrict__ gamma, const float* __restrict__ beta) {
    int c = threadIdx.x;
    if (c < Dd) {
        float mean = g_sum[c] / (float)Nn;
        float var = g_sumsq[c] / (float)Nn - mean * mean;
        float rstd = rsqrtf(var + BN_EPS);
        float sc = rstd * gamma[c];
        g_scale[c] = sc;
        g_shift[c] = beta[c] - mean * sc;
    }
}

__global__ void bn_apply_kernel(const float* __restrict__ a, const float* __restrict__ b,
                                float* __restrict__ o) {
    size_t idx = (size_t)blockIdx.x * blockDim.x + threadIdx.x;
    size_t stride = (size_t)gridDim.x * blockDim.x;
    size_t total = (size_t)Nn * Dd;
    for (; idx < total; idx += stride) {
        int col = (int)(idx & (Dd - 1));
        o[idx] = (a[idx] + b[idx]) * g_scale[col] + g_shift[col];
    }
}

// ---------------- final projection [N,128] @ [128,5] + bias ----------------
__global__ void proj_kernel(const float* __restrict__ x, const float* __restrict__ Wp,
                            const float* __restrict__ bp, float* __restrict__ out) {
    __shared__ float w[Dd * CC];
    for (int i = threadIdx.x; i < Dd * CC; i += blockDim.x) w[i] = Wp[i];
    __syncthreads();
    int n = blockIdx.x * blockDim.x + threadIdx.x;
    if (n >= Nn) return;
    float acc[CC];
#pragma unroll
    for (int c = 0; c < CC; c++) acc[c] = bp[c];
    const float* xr = x + (size_t)n * Dd;
    for (int kk = 0; kk < Dd; kk += 4) {
        float4 xv = *(const float4*)(xr + kk);
#pragma unroll
        for (int c = 0; c < CC; c++) {
            acc[c] += xv.x * w[(kk + 0) * CC + c];
            acc[c] += xv.y * w[(kk + 1) * CC + c];
            acc[c] += xv.z * w[(kk + 2) * CC + c];
            acc[c] += xv.w * w[(kk + 3) * CC + c];
        }
    }
#pragma unroll
    for (int c = 0; c < CC; c++) out[(size_t)n * CC + c] = acc[c];
}

// ---------------- driver ----------------
extern "C" void kernel_launch(void* const* d_in, const int* in_sizes, int n_in,
                              void* d_out, int out_size) {
    const float* x_in = (const float*)d_in[0];
    const int* eidx = (const int*)d_in[1];
    const float* Wq = (const float*)d_in[2];
    const float* Wk = (const float*)d_in[3];
    const float* Wv = (const float*)d_in[4];
    const float* Wo = (const float*)d_in[5];
    const float* g1 = (const float*)d_in[6];
    const float* bn1 = (const float*)d_in[7];
    const float* W1 = (const float*)d_in[8];
    const float* bf1 = (const float*)d_in[9];
    const float* W2 = (const float*)d_in[10];
    const float* bf2 = (const float*)d_in[11];
    const float* g2 = (const float*)d_in[12];
    const float* bn2 = (const float*)d_in[13];
    const float* Wp = (const float*)d_in[14];
    const float* bp = (const float*)d_in[15];
    float* out = (float*)d_out;

    const int* src = eidx;        // edge_index[0]
    const int* dst = eidx + Ee;   // edge_index[1]

    const int MB = (Nn + 127) / 128;        // 391
    dim3 gridQKV(MB, 1, 3);
    dim3 grid128(MB, 1, 1);
    dim3 gridFF1(MB, 2, 1);
    int attnBlocks = (Nn * 32 + 255) / 256;

    // launch 1: layer-0 fused QKV (reads x_in directly; independent of CSR)
    gemm_kernel<<<gridQKV, 256>>>(x_in, Wq, Wk, Wv, nullptr,
                                  g_Q, g_K, g_V, Nn, Dd, Dd, 0);
    // launch 2: whole CSR build in one kernel
    csr_build_kernel<<<1, 1024>>>(src, dst);
    // launch 3: BN sums zero (needed for layer-0 first BN anyway)
    zero_sums_kernel<<<1, 128>>>();
    // launch 4: layer-0 attention  <-- ncu captures the 4th launch
    attn_kernel<<<attnBlocks, 256>>>(g_Q, g_K, g_V, g_ATT);

    for (int i = 0; i < LL; i++) {
        const float* Wo_i = Wo + (size_t)i * Dd * Dd;
        const float* W1_i = W1 + (size_t)i * Dd * FFd;
        const float* W2_i = W2 + (size_t)i * FFd * Dd;
        const float* res = (i == 0) ? x_in : g_X;   // layer-0 residual = raw input

        if (i > 0) {
            gemm_kernel<<<gridQKV, 256>>>(g_X,
                                          Wq + (size_t)i * Dd * Dd,
                                          Wk + (size_t)i * Dd * Dd,
                                          Wv + (size_t)i * Dd * Dd,
                                          nullptr, g_Q, g_K, g_V, Nn, Dd, Dd, 0);
            attn_kernel<<<attnBlocks, 256>>>(g_Q, g_K, g_V, g_ATT);
        }

        gemm_kernel<<<grid128, 256>>>(g_ATT, Wo_i, nullptr, nullptr, nullptr,
                                      g_A, nullptr, nullptr, Nn, Dd, Dd, 0);

        // x = BN(a + res)   (zero_sums for i==0 first BN already issued at launch 3)
        if (i > 0) zero_sums_kernel<<<1, 128>>>();
        bn_reduce_kernel<<<1024, 128>>>(g_A, res);
        bn_finalize_kernel<<<1, 128>>>(g1 + (size_t)i * Dd, bn1 + (size_t)i * Dd);
        bn_apply_kernel<<<2048, 256>>>(g_A, res, g_X);

        // h = relu(x@W1 + bf1); t = h@W2 + bf2
        gemm_kernel<<<gridFF1, 256>>>(g_X, W1_i, nullptr, nullptr, bf1 + (size_t)i * FFd,
                                      g_Hbuf, nullptr, nullptr, Nn, Dd, FFd, 1);
        gemm_kernel<<<grid128, 256>>>(g_Hbuf, W2_i, nullptr, nullptr, bf2 + (size_t)i * Dd,
                                      g_T, nullptr, nullptr, Nn, FFd, Dd, 0);

        // x = BN(x + t)
        zero_sums_kernel<<<1, 128>>>();
        bn_reduce_kernel<<<1024, 128>>>(g_X, g_T);
        bn_finalize_kernel<<<1, 128>>>(g2 + (size_t)i * Dd, bn2 + (size_t)i * Dd);
        bn_apply_kernel<<<2048, 256>>>(g_X, g_T, g_X);
    }

    proj_kernel<<<(Nn + 255) / 256, 256>>>(g_X, Wp, bp, out);

    (void)in_sizes; (void)n_in; (void)out_size;
}

// round 10
// speedup vs baseline: 1.5515x; 1.3662x over previous
#include <cuda_runtime.h>
#include <math.h>
#include <stdint.h>

#define Nn 50000
#define Ee 640000
#define Dd 128
#define FFd 256
#define CC 5
#define LL 6
#define BN_EPS 1e-5f

// ---------------- static scratch (no allocations allowed) ----------------
__device__ float g_X[(size_t)Nn * Dd];
__device__ float g_Q[(size_t)Nn * Dd];
__device__ float g_K[(size_t)Nn * Dd];
__device__ float g_V[(size_t)Nn * Dd];
__device__ float g_ATT[(size_t)Nn * Dd];
__device__ float g_A[(size_t)Nn * Dd];
__device__ float g_Hbuf[(size_t)Nn * FFd];
__device__ float g_T[(size_t)Nn * Dd];

__device__ int g_cnt[Nn];
__device__ int g_fill[Nn];
__device__ int g_rowptr[Nn + 1];
__device__ int g_esrc[Ee];
__device__ int g_blocksum[64];

__device__ float g_sum[Dd];
__device__ float g_sumsq[Dd];
__device__ float g_scale[Dd];
__device__ float g_shift[Dd];

// ---------------- CSR build (multi-kernel, measured-fast) ----------------
__global__ void zero_csr_kernel() {
    int i = blockIdx.x * blockDim.x + threadIdx.x;
    int stride = gridDim.x * blockDim.x;
    for (; i < Nn; i += stride) { g_cnt[i] = 0; g_fill[i] = 0; }
}

__global__ void count_kernel(const int* __restrict__ dst) {
    int e = blockIdx.x * blockDim.x + threadIdx.x;
    if (e < Ee) atomicAdd(&g_cnt[dst[e]], 1);
}

__global__ void scan_chunk_kernel() {
    __shared__ int s[1024];
    int tid = threadIdx.x;
    int i = blockIdx.x * 1024 + tid;
    int v = (i < Nn) ? g_cnt[i] : 0;
    s[tid] = v;
    __syncthreads();
    for (int off = 1; off < 1024; off <<= 1) {
        int t = 0;
        if (tid >= off) t = s[tid - off];
        __syncthreads();
        s[tid] += t;
        __syncthreads();
    }
    if (i < Nn) g_rowptr[i + 1] = s[tid];
    if (tid == 1023) g_blocksum[blockIdx.x] = s[1023];
    if (blockIdx.x == 0 && tid == 0) g_rowptr[0] = 0;
}

__global__ void scan_blocks_kernel(int numChunks) {
    if (threadIdx.x == 0 && blockIdx.x == 0) {
        int run = 0;
        for (int c = 0; c < numChunks; c++) {
            int t = g_blocksum[c];
            g_blocksum[c] = run;
            run += t;
        }
    }
}

__global__ void scan_add_kernel() {
    int i = blockIdx.x * blockDim.x + threadIdx.x;
    if (i < Nn) g_rowptr[i + 1] += g_blocksum[i >> 10];
}

__global__ void fill_kernel(const int* __restrict__ src, const int* __restrict__ dst) {
    int e = blockIdx.x * blockDim.x + threadIdx.x;
    if (e < Ee) {
        int d = dst[e];
        int pos = atomicAdd(&g_fill[d], 1);
        g_esrc[g_rowptr[d] + pos] = src[e];
    }
}

// ---------------- GEMM v3: conflict-free warp-tiled fp32 ----------------
// C[M,Nc] = A[M,K] @ B[K,Nc] (+bias)(+relu). BM=BN=128, BK=16, 256 threads.
// 8 warps as 4(M)x2(N): warp tile 32x64. Lane 4x8: micro 8x8 = 2x2 of 4x4:
//   m = wm*32 + (lane>>3)*4 + mi*16 + i,  n = wn*64 + (lane&7)*4 + ni*32 + j
// A-frag LDS: broadcast per phase. B-frag LDS: banks 0-31 unique per phase.
// Double-buffered smem; blockIdx.z selects (B,C) -> fused QKV.
#define ALD 132

__global__ __launch_bounds__(256) void gemm_kernel(
    const float* __restrict__ A,
    const float* __restrict__ B0, const float* __restrict__ B1, const float* __restrict__ B2,
    const float* __restrict__ bias,
    float* __restrict__ C0, float* __restrict__ C1, float* __restrict__ C2,
    int M, int K, int Nc, int fuseRelu)
{
    const float* B = (blockIdx.z == 0) ? B0 : ((blockIdx.z == 1) ? B1 : B2);
    float* C = (blockIdx.z == 0) ? C0 : ((blockIdx.z == 1) ? C1 : C2);

    __shared__ float As[2][16][ALD];   // [k][m], padded
    __shared__ float Bs[2][16][128];   // [k][n]

    const int tid = threadIdx.x;
    const int bm = blockIdx.x * 128;
    const int bn = blockIdx.y * 128;

    const int lane = tid & 31;
    const int wid = tid >> 5;          // 0..7
    const int wm = wid & 3;            // 4 M-slabs
    const int wn = wid >> 2;           // 2 N-slabs
    const int lm = (lane >> 3) * 4;    // 0,4,8,12
    const int ln = (lane & 7) * 4;     // 0..28
    const int mbase = wm * 32 + lm;    // + {0,16}
    const int nbase = wn * 64 + ln;    // + {0,32}

    // --- loader mapping ---
    // A: thread t -> m = t&127, kq = t>>7; loads A[m][kq*8 + {0..3,4..7}]
    const int am = tid & 127;
    const int akq = (tid >> 7) * 8;
    const bool avalid = (bm + am) < M;
    const float* Aptr = A + (size_t)(bm + am) * K + akq;
    // B: thread t -> r = t>>5 (0..7), c4 = t&31; loads rows r and r+8
    const int br = tid >> 5;
    const int bc = (tid & 31) * 4;
    const float* Bptr = B + (size_t)br * Nc + bn + bc;

    float acc[2][2][4][4];
#pragma unroll
    for (int a = 0; a < 2; a++)
#pragma unroll
        for (int b = 0; b < 2; b++)
#pragma unroll
            for (int i = 0; i < 4; i++)
#pragma unroll
                for (int j = 0; j < 4; j++) acc[a][b][i][j] = 0.f;

    // ---- preload tile 0 ----
    {
        float4 a0 = make_float4(0.f, 0.f, 0.f, 0.f), a1 = a0;
        if (avalid) { a0 = *(const float4*)(Aptr); a1 = *(const float4*)(Aptr + 4); }
        float4 b0 = *(const float4*)(Bptr);
        float4 b1 = *(const float4*)(Bptr + (size_t)8 * Nc);
        As[0][akq + 0][am] = a0.x; As[0][akq + 1][am] = a0.y;
        As[0][akq + 2][am] = a0.z; As[0][akq + 3][am] = a0.w;
        As[0][akq + 4][am] = a1.x; As[0][akq + 5][am] = a1.y;
        As[0][akq + 6][am] = a1.z; As[0][akq + 7][am] = a1.w;
        *(float4*)&Bs[0][br][bc] = b0;
        *(float4*)&Bs[0][br + 8][bc] = b1;
    }
    __syncthreads();

    int cur = 0;
    for (int k0 = 0; k0 < K; k0 += 16) {
        const bool has = (k0 + 16) < K;
        float4 a0n, a1n, b0n, b1n;
        if (has) {
            a0n = make_float4(0.f, 0.f, 0.f, 0.f); a1n = a0n;
            if (avalid) {
                a0n = *(const float4*)(Aptr + k0 + 16);
                a1n = *(const float4*)(Aptr + k0 + 20);
            }
            b0n = *(const float4*)(Bptr + (size_t)(k0 + 16) * Nc);
            b1n = *(const float4*)(Bptr + (size_t)(k0 + 24) * Nc);
        }

#pragma unroll
        for (int k = 0; k < 16; k++) {
            float af[2][4], bf[2][4];
            *(float4*)&af[0][0] = *(const float4*)&As[cur][k][mbase];
            *(float4*)&af[1][0] = *(const float4*)&As[cur][k][mbase + 16];
            *(float4*)&bf[0][0] = *(const float4*)&Bs[cur][k][nbase];
            *(float4*)&bf[1][0] = *(const float4*)&Bs[cur][k][nbase + 32];
#pragma unroll
            for (int a = 0; a < 2; a++)
#pragma unroll
                for (int b = 0; b < 2; b++)
#pragma unroll
                    for (int i = 0; i < 4; i++)
#pragma unroll
                        for (int j = 0; j < 4; j++)
                            acc[a][b][i][j] += af[a][i] * bf[b][j];
        }

        if (has) {
            int nxt = cur ^ 1;
            As[nxt][akq + 0][am] = a0n.x; As[nxt][akq + 1][am] = a0n.y;
            As[nxt][akq + 2][am] = a0n.z; As[nxt][akq + 3][am] = a0n.w;
            As[nxt][akq + 4][am] = a1n.x; As[nxt][akq + 5][am] = a1n.y;
            As[nxt][akq + 6][am] = a1n.z; As[nxt][akq + 7][am] = a1n.w;
            *(float4*)&Bs[nxt][br][bc] = b0n;
            *(float4*)&Bs[nxt][br + 8][bc] = b1n;
            __syncthreads();
            cur = nxt;
        }
    }

    // ---- epilogue ----
    float bv[2][4];
#pragma unroll
    for (int b = 0; b < 2; b++)
#pragma unroll
        for (int j = 0; j < 4; j++)
            bv[b][j] = bias ? bias[bn + nbase + b * 32 + j] : 0.f;

#pragma unroll
    for (int a = 0; a < 2; a++)
#pragma unroll
        for (int i = 0; i < 4; i++) {
            int row = bm + mbase + a * 16 + i;
            if (row < M) {
#pragma unroll
                for (int b = 0; b < 2; b++) {
                    float o[4];
#pragma unroll
                    for (int j = 0; j < 4; j++) {
                        float vvv = acc[a][b][i][j] + bv[b][j];
                        if (fuseRelu) vvv = fmaxf(vvv, 0.f);
                        o[j] = vvv;
                    }
                    *(float4*)&C[(size_t)row * Nc + bn + nbase + b * 32] = *(float4*)&o[0];
                }
            }
        }
}

// ---------------- edge-restricted MHA: one warp per dst node, 2-edge unrolled ---------
__global__ __launch_bounds__(256) void attn_kernel(
    const float* __restrict__ q, const float* __restrict__ k,
    const float* __restrict__ v, float* __restrict__ out)
{
    int gwarp = (blockIdx.x * blockDim.x + threadIdx.x) >> 5;
    if (gwarp >= Nn) return;
    int lane = threadIdx.x & 31;

    float4 qv = *(const float4*)(q + (size_t)gwarp * Dd + lane * 4);
    float m = -INFINITY;
    float l = 0.f;
    float4 acc = make_float4(0.f, 0.f, 0.f, 0.f);

    const int beg = g_rowptr[gwarp];
    const int end = g_rowptr[gwarp + 1];
    int it = beg;

    for (; it + 2 <= end; it += 2) {
        int sn0 = g_esrc[it];
        int sn1 = g_esrc[it + 1];
        const float4 kv0 = *(const float4*)(k + (size_t)sn0 * Dd + lane * 4);
        const float4 kv1 = *(const float4*)(k + (size_t)sn1 * Dd + lane * 4);
        const float4 vv0 = *(const float4*)(v + (size_t)sn0 * Dd + lane * 4);
        const float4 vv1 = *(const float4*)(v + (size_t)sn1 * Dd + lane * 4);

        float p0 = qv.x * kv0.x + qv.y * kv0.y + qv.z * kv0.z + qv.w * kv0.w;
        float p1 = qv.x * kv1.x + qv.y * kv1.y + qv.z * kv1.z + qv.w * kv1.w;
        p0 += __shfl_xor_sync(0xffffffffu, p0, 1);
        p1 += __shfl_xor_sync(0xffffffffu, p1, 1);
        p0 += __shfl_xor_sync(0xffffffffu, p0, 2);
        p1 += __shfl_xor_sync(0xffffffffu, p1, 2);
        float s0 = p0 * 0.25f;
        float s1 = p1 * 0.25f;

        float nm = fmaxf(m, fmaxf(s0, s1));
        float sc = __expf(m - nm);
        float e0 = __expf(s0 - nm);
        float e1 = __expf(s1 - nm);
        l = l * sc + e0 + e1;
        acc.x = acc.x * sc + e0 * vv0.x + e1 * vv1.x;
        acc.y = acc.y * sc + e0 * vv0.y + e1 * vv1.y;
        acc.z = acc.z * sc + e0 * vv0.z + e1 * vv1.z;
        acc.w = acc.w * sc + e0 * vv0.w + e1 * vv1.w;
        m = nm;
    }

    if (it < end) {
        int sn = g_esrc[it];
        const float4 kv = *(const float4*)(k + (size_t)sn * Dd + lane * 4);
        const float4 vv = *(const float4*)(v + (size_t)sn * Dd + lane * 4);
        float p = qv.x * kv.x + qv.y * kv.y + qv.z * kv.z + qv.w * kv.w;
        p += __shfl_xor_sync(0xffffffffu, p, 1);
        p += __shfl_xor_sync(0xffffffffu, p, 2);
        float ss = p * 0.25f;
        float nm = fmaxf(m, ss);
        float sc = __expf(m - nm);
        float e = __expf(ss - nm);
        l = l * sc + e;
        acc.x = acc.x * sc + e * vv.x;
        acc.y = acc.y * sc + e * vv.y;
        acc.z = acc.z * sc + e * vv.z;
        acc.w = acc.w * sc + e * vv.w;
        m = nm;
    }

    float inv = (l > 0.f) ? (1.f / l) : 0.f;
    float4 o = make_float4(acc.x * inv, acc.y * inv, acc.z * inv, acc.w * inv);
    *(float4*)(out + (size_t)gwarp * Dd + lane * 4) = o;
}

// ---------------- BatchNorm (training-mode, over node dim) ----------------
__global__ void zero_sums_kernel() {
    int t = threadIdx.x;
    if (t < Dd) { g_sum[t] = 0.f; g_sumsq[t] = 0.f; }
}

__global__ void bn_reduce_kernel(const float* __restrict__ a, const float* __restrict__ b) {
    int col = threadIdx.x;  // 128 threads
    int rows = (Nn + gridDim.x - 1) / gridDim.x;
    int r0 = blockIdx.x * rows;
    int r1 = r0 + rows; if (r1 > Nn) r1 = Nn;
    float s = 0.f, s2 = 0.f;
    for (int r = r0; r < r1; r++) {
        float t = a[(size_t)r * Dd + col] + b[(size_t)r * Dd + col];
        s += t;
        s2 += t * t;
    }
    atomicAdd(&g_sum[col], s);
    atomicAdd(&g_sumsq[col], s2);
}

__global__ void bn_finalize_kernel(const float* __restrict__ gamma, const float* __restrict__ beta) {
    int c = threadIdx.x;
    if (c < Dd) {
        float mean = g_sum[c] / (float)Nn;
        float var = g_sumsq[c] / (float)Nn - mean * mean;
        float rstd = rsqrtf(var + BN_EPS);
        float sc = rstd * gamma[c];
        g_scale[c] = sc;
        g_shift[c] = beta[c] - mean * sc;
    }
}

__global__ void bn_apply_kernel(const float* __restrict__ a, const float* __restrict__ b,
                                float* __restrict__ o) {
    size_t idx = (size_t)blockIdx.x * blockDim.x + threadIdx.x;
    size_t stride = (size_t)gridDim.x * blockDim.x;
    size_t total = (size_t)Nn * Dd;
    for (; idx < total; idx += stride) {
        int col = (int)(idx & (Dd - 1));
        o[idx] = (a[idx] + b[idx]) * g_scale[col] + g_shift[col];
    }
}

// ---------------- final projection [N,128] @ [128,5] + bias ----------------
__global__ void proj_kernel(const float* __restrict__ x, const float* __restrict__ Wp,
                            const float* __restrict__ bp, float* __restrict__ out) {
    __shared__ float w[Dd * CC];
    for (int i = threadIdx.x; i < Dd * CC; i += blockDim.x) w[i] = Wp[i];
    __syncthreads();
    int n = blockIdx.x * blockDim.x + threadIdx.x;
    if (n >= Nn) return;
    float acc[CC];
#pragma unroll
    for (int c = 0; c < CC; c++) acc[c] = bp[c];
    const float* xr = x + (size_t)n * Dd;
    for (int kk = 0; kk < Dd; kk += 4) {
        float4 xv = *(const float4*)(xr + kk);
#pragma unroll
        for (int c = 0; c < CC; c++) {
            acc[c] += xv.x * w[(kk + 0) * CC + c];
            acc[c] += xv.y * w[(kk + 1) * CC + c];
            acc[c] += xv.z * w[(kk + 2) * CC + c];
            acc[c] += xv.w * w[(kk + 3) * CC + c];
        }
    }
#pragma unroll
    for (int c = 0; c < CC; c++) out[(size_t)n * CC + c] = acc[c];
}

// ---------------- driver ----------------
extern "C" void kernel_launch(void* const* d_in, const int* in_sizes, int n_in,
                              void* d_out, int out_size) {
    const float* x_in = (const float*)d_in[0];
    const int* eidx = (const int*)d_in[1];
    const float* Wq = (const float*)d_in[2];
    const float* Wk = (const float*)d_in[3];
    const float* Wv = (const float*)d_in[4];
    const float* Wo = (const float*)d_in[5];
    const float* g1 = (const float*)d_in[6];
    const float* bn1 = (const float*)d_in[7];
    const float* W1 = (const float*)d_in[8];
    const float* bf1 = (const float*)d_in[9];
    const float* W2 = (const float*)d_in[10];
    const float* bf2 = (const float*)d_in[11];
    const float* g2 = (const float*)d_in[12];
    const float* bn2 = (const float*)d_in[13];
    const float* Wp = (const float*)d_in[14];
    const float* bp = (const float*)d_in[15];
    float* out = (float*)d_out;

    const int* src = eidx;        // edge_index[0]
    const int* dst = eidx + Ee;   // edge_index[1]

    const int MB = (Nn + 127) / 128;        // 391
    dim3 gridQKV(MB, 1, 3);
    dim3 grid128(MB, 1, 1);
    dim3 gridFF1(MB, 2, 1);
    int attnBlocks = (Nn * 32 + 255) / 256;
    int numChunks = (Nn + 1023) / 1024;     // 49

    // launches 1-3: CSR first half
    zero_csr_kernel<<<256, 256>>>();
    count_kernel<<<(Ee + 255) / 256, 256>>>(dst);
    scan_chunk_kernel<<<numChunks, 1024>>>();
    // launch 4: layer-0 fused QKV GEMM  <-- profiler slot
    gemm_kernel<<<gridQKV, 256>>>(x_in, Wq, Wk, Wv, nullptr,
                                  g_Q, g_K, g_V, Nn, Dd, Dd, 0);
    // CSR second half (all before first attn; stream-ordered)
    scan_blocks_kernel<<<1, 32>>>(numChunks);
    scan_add_kernel<<<(Nn + 255) / 256, 256>>>();
    fill_kernel<<<(Ee + 255) / 256, 256>>>(src, dst);

    for (int i = 0; i < LL; i++) {
        const float* Wo_i = Wo + (size_t)i * Dd * Dd;
        const float* W1_i = W1 + (size_t)i * Dd * FFd;
        const float* W2_i = W2 + (size_t)i * FFd * Dd;
        const float* res = (i == 0) ? x_in : g_X;   // layer-0 residual = raw input

        if (i > 0) {
            gemm_kernel<<<gridQKV, 256>>>(g_X,
                                          Wq + (size_t)i * Dd * Dd,
                                          Wk + (size_t)i * Dd * Dd,
                                          Wv + (size_t)i * Dd * Dd,
                                          nullptr, g_Q, g_K, g_V, Nn, Dd, Dd, 0);
        }

        attn_kernel<<<attnBlocks, 256>>>(g_Q, g_K, g_V, g_ATT);

        gemm_kernel<<<grid128, 256>>>(g_ATT, Wo_i, nullptr, nullptr, nullptr,
                                      g_A, nullptr, nullptr, Nn, Dd, Dd, 0);

        // x = BN(a + res)
        zero_sums_kernel<<<1, 128>>>();
        bn_reduce_kernel<<<1024, 128>>>(g_A, res);
        bn_finalize_kernel<<<1, 128>>>(g1 + (size_t)i * Dd, bn1 + (size_t)i * Dd);
        bn_apply_kernel<<<2048, 256>>>(g_A, res, g_X);

        // h = relu(x@W1 + bf1); t = h@W2 + bf2
        gemm_kernel<<<gridFF1, 256>>>(g_X, W1_i, nullptr, nullptr, bf1 + (size_t)i * FFd,
                                      g_Hbuf, nullptr, nullptr, Nn, Dd, FFd, 1);
        gemm_kernel<<<grid128, 256>>>(g_Hbuf, W2_i, nullptr, nullptr, bf2 + (size_t)i * Dd,
                                      g_T, nullptr, nullptr, Nn, FFd, Dd, 0);

        // x = BN(x + t)
        zero_sums_kernel<<<1, 128>>>();
        bn_reduce_kernel<<<1024, 128>>>(g_X, g_T);
        bn_finalize_kernel<<<1, 128>>>(g2 + (size_t)i * Dd, bn2 + (size_t)i * Dd);
        bn_apply_kernel<<<2048, 256>>>(g_X, g_T, g_X);
    }

    proj_kernel<<<(Nn + 255) / 256, 256>>>(g_X, Wp, bp, out);

    (void)in_sizes; (void)n_in; (void)out_size;
}